// round 17
// baseline (speedup 1.0000x reference)
#include <cuda_runtime.h>
#include <cuda_fp16.h>
#include <math.h>
#include <stdint.h>

#define BB 2
#define NQ 2048
#define NK 2048
#define DD 1024
#define HH 16
#define HDIM 64

// Scratch (allocation-free: __device__ globals), all fp16 at rest.
__device__ __half g_Q[(size_t)BB * NQ * DD];
__device__ __half g_K[(size_t)BB * NK * DD];
__device__ __half g_V[(size_t)BB * NK * DD];
__device__ __half g_O[(size_t)BB * NQ * DD];
__device__ __half g_Xq[(size_t)BB * NQ * DD];
__device__ __half g_Xkv[(size_t)BB * NK * DD];
__device__ __half g_Wq[(size_t)DD * DD];
__device__ __half g_Wk[(size_t)DD * DD];
__device__ __half g_Wv[(size_t)DD * DD];
__device__ __half g_Wo[(size_t)DD * DD];

// ---------------------------------------------------------------------------
// helpers
// ---------------------------------------------------------------------------
__device__ __forceinline__ uint32_t packh2(float a, float b) {
    __half2 h = __floats2half2_rn(a, b);
    return *(uint32_t*)&h;
}

__device__ __forceinline__ void mma16(float c[4], const uint32_t a[4], const uint32_t b[2]) {
    asm volatile(
        "mma.sync.aligned.m16n8k16.row.col.f32.f16.f16.f32 "
        "{%0,%1,%2,%3}, {%4,%5,%6,%7}, {%8,%9}, {%0,%1,%2,%3};\n"
        : "+f"(c[0]), "+f"(c[1]), "+f"(c[2]), "+f"(c[3])
        : "r"(a[0]), "r"(a[1]), "r"(a[2]), "r"(a[3]), "r"(b[0]), "r"(b[1]));
}

__device__ __forceinline__ void ldsm4(uint32_t a[4], uint32_t addr) {
    asm volatile("ldmatrix.sync.aligned.m8n8.x4.shared.b16 {%0,%1,%2,%3}, [%4];"
                 : "=r"(a[0]), "=r"(a[1]), "=r"(a[2]), "=r"(a[3]) : "r"(addr));
}
__device__ __forceinline__ void ldsm2(uint32_t b[2], uint32_t addr) {
    asm volatile("ldmatrix.sync.aligned.m8n8.x2.shared.b16 {%0,%1}, [%2];"
                 : "=r"(b[0]), "=r"(b[1]) : "r"(addr));
}
__device__ __forceinline__ void ldsm2t(uint32_t b[2], uint32_t addr) {
    asm volatile("ldmatrix.sync.aligned.m8n8.x2.trans.shared.b16 {%0,%1}, [%2];"
                 : "=r"(b[0]), "=r"(b[1]) : "r"(addr));
}

__device__ __forceinline__ void cpa16(uint32_t dst_smem, const void* src) {
    asm volatile("cp.async.cg.shared.global [%0], [%1], 16;\n" :: "r"(dst_smem), "l"(src));
}
__device__ __forceinline__ void cp_commit() {
    asm volatile("cp.async.commit_group;\n");
}
__device__ __forceinline__ void cp_wait0() { asm volatile("cp.async.wait_group 0;\n"); }
__device__ __forceinline__ void cp_wait1() { asm volatile("cp.async.wait_group 1;\n"); }
__device__ __forceinline__ void cp_wait2() { asm volatile("cp.async.wait_group 2;\n"); }

__device__ __forceinline__ void stcs2(float* p, float a, float b) {
    asm volatile("st.global.cs.v2.f32 [%0], {%1,%2};\n" :: "l"(p), "f"(a), "f"(b));
}

extern __shared__ char smraw[];

// ---------------------------------------------------------------------------
// Fused fp32 -> fp16 converter for all 6 inputs (one launch).
// ---------------------------------------------------------------------------
#define SEQ4 ((BB * NQ * DD) / 4)
#define W4   ((DD * DD) / 4)
#define CVT_TOTAL (2 * SEQ4 + 4 * W4)

__global__ void cvt_all_kernel(const float4* q, const float4* kv,
                               const float4* w0, const float4* w1,
                               const float4* w2, const float4* w3,
                               uint2* dq, uint2* dkv,
                               uint2* dw0, uint2* dw1, uint2* dw2, uint2* dw3) {
    int i = blockIdx.x * blockDim.x + threadIdx.x;
    if (i >= CVT_TOTAL) return;
    const float4* s; uint2* d; int off;
    if (i < SEQ4)            { s = q;  d = dq;  off = i; }
    else if (i < 2 * SEQ4)   { s = kv; d = dkv; off = i - SEQ4; }
    else {
        int j = i - 2 * SEQ4;
        int w = j / W4; off = j - w * W4;
        s = (w == 0) ? w0 : (w == 1) ? w1 : (w == 2) ? w2 : w3;
        d = (w == 0) ? dw0 : (w == 1) ? dw1 : (w == 2) ? dw2 : dw3;
    }
    float4 v = s[off];
    d[off] = make_uint2(packh2(v.x, v.y), packh2(v.z, v.w));
}

// ---------------------------------------------------------------------------
// Tensor-core GEMM (fp16 in, fp32 acc) + optional fused xpos-RoPE epilogue.
// 128x128 tile (256 blocks = 1 full wave @ 2 CTAs/SM), k-tile 64,
// cp.async double-buffered, 8 warps 2x4, warp tile 64x32. (R15, known-good)
// ---------------------------------------------------------------------------
#define GBM 128
#define GBN 128
#define GBK 64
#define GPADH 72
#define GEMM_SMEM (2 * (GBM * GPADH + GBN * GPADH) * 2)   // 73728

__global__ void __launch_bounds__(256, 2)
gemm_bias_rope_tc(const __half* __restrict__ X, const __half* __restrict__ W,
                  const float* __restrict__ bias, void* __restrict__ Yout,
                  int M, int N, int K,
                  const float* __restrict__ freqs, float scale_base, float rsign,
                  int do_rope, int out_f16, float prescale) {
    int tid = threadIdx.x;
    int warp = tid >> 5, lane = tid & 31;
    int g = lane >> 2, tig = lane & 3;
    int wm = warp >> 2, wn = warp & 3;     // 2 x 4 warps, tile 64x32
    int row0 = blockIdx.y * GBM, col0 = blockIdx.x * GBN;

    uint32_t xsB = (uint32_t)__cvta_generic_to_shared(smraw);
    uint32_t wsB = xsB + 2 * GBM * GPADH * 2;

    uint32_t aOff = ((wm * 64 + (lane & 15)) * GPADH + (lane >> 4) * 8) * 2;
    uint32_t bOff = ((wn * 32 + (lane & 7)) * GPADH + ((lane >> 3) & 1) * 8) * 2;

    float acc[4][4][4] = {};

#define GSTAGE(buf, kt)                                                          \
    do {                                                                         \
        _Pragma("unroll")                                                        \
        for (int i = 0; i < 4; i++) {                                            \
            int idx = tid + i * 256;                                             \
            int r = idx >> 3, c8 = (idx & 7) * 8;                                \
            cpa16(xsB + ((buf) * GBM * GPADH + r * GPADH + c8) * 2,              \
                  X + (size_t)(row0 + r) * K + (kt) + c8);                       \
        }                                                                        \
        _Pragma("unroll")                                                        \
        for (int i = 0; i < 4; i++) {                                            \
            int idx = tid + i * 256;                                             \
            int r = idx >> 3, c8 = (idx & 7) * 8;                                \
            cpa16(wsB + ((buf) * GBN * GPADH + r * GPADH + c8) * 2,              \
                  W + (size_t)(col0 + r) * K + (kt) + c8);                       \
        }                                                                        \
        cp_commit();                                                             \
    } while (0)

    GSTAGE(0, 0);
    int T = K / GBK;
    for (int t = 0; t < T; t++) {
        if (t + 1 < T) { GSTAGE((t + 1) & 1, (t + 1) * GBK); cp_wait1(); }
        else           { cp_wait0(); }
        __syncthreads();
        uint32_t xb = xsB + (t & 1) * GBM * GPADH * 2 + aOff;
        uint32_t wb = wsB + (t & 1) * GBN * GPADH * 2 + bOff;
#pragma unroll
        for (int ks = 0; ks < 4; ks++) {
            int k0 = ks * 16;
            uint32_t a[4][4], bf[4][2];
#pragma unroll
            for (int mi = 0; mi < 4; mi++)
                ldsm4(a[mi], xb + (mi * 16 * GPADH + k0) * 2);
#pragma unroll
            for (int ni = 0; ni < 4; ni++)
                ldsm2(bf[ni], wb + (ni * 8 * GPADH + k0) * 2);
#pragma unroll
            for (int mi = 0; mi < 4; mi++)
#pragma unroll
                for (int ni = 0; ni < 4; ni++)
                    mma16(acc[mi][ni], a[mi], bf[ni]);
        }
        __syncthreads();
    }
#undef GSTAGE

#pragma unroll
    for (int mi = 0; mi < 4; mi++) {
        int r = row0 + wm * 64 + mi * 16 + g;
#pragma unroll
        for (int ni = 0; ni < 4; ni++) {
            int c = col0 + wn * 32 + ni * 8 + tig * 2;
            float v0 = acc[mi][ni][0] + bias[c];
            float v1 = acc[mi][ni][1] + bias[c + 1];
            float v2 = acc[mi][ni][2] + bias[c];
            float v3 = acc[mi][ni][3] + bias[c + 1];
            if (do_rope) {
                int cd = c & (HDIM - 1);
                float f = freqs[cd >> 1];
                float sv = ((float)cd + 0.4f * (float)HDIM) / (1.4f * (float)HDIM);
                {
                    float n0 = (float)(r & (NQ - 1));
                    float sn, cs; sincosf(n0 * f, &sn, &cs);
                    float scale = powf(sv, (n0 - (float)(NQ / 2)) / scale_base * rsign);
                    float o0 = (v0 * cs - v1 * sn) * scale;
                    float o1 = (v1 * cs + v0 * sn) * scale;
                    v0 = o0; v1 = o1;
                }
                {
                    float n1 = (float)((r + 8) & (NQ - 1));
                    float sn, cs; sincosf(n1 * f, &sn, &cs);
                    float scale = powf(sv, (n1 - (float)(NQ / 2)) / scale_base * rsign);
                    float o2 = (v2 * cs - v3 * sn) * scale;
                    float o3 = (v3 * cs + v2 * sn) * scale;
                    v2 = o2; v3 = o3;
                }
            }
            if (out_f16) {
                __half* Y = (__half*)Yout;
                *(uint32_t*)(Y + (size_t)r * N + c) = packh2(v0 * prescale, v1 * prescale);
                *(uint32_t*)(Y + (size_t)(r + 8) * N + c) = packh2(v2 * prescale, v3 * prescale);
            } else {
                float* Y = (float*)Yout;
                *(float2*)(Y + (size_t)r * N + c) = make_float2(v0, v1);
                *(float2*)(Y + (size_t)(r + 8) * N + c) = make_float2(v2, v3);
            }
        }
    }
}

// ---------------------------------------------------------------------------
// Fused attention: 64-row q-tiles, 64-row k-tiles, 4 CTAs/SM (<=64 regs:
// Q fragments re-loaded via ldmatrix per ks instead of register residency).
// 256 threads. S: 2x4 warp grid (32x16 tiles); PV: 4x2 (16x32 tiles).
// ---------------------------------------------------------------------------
#define QROWS 64
#define KT 64
#define NKT (NK / KT)          // 32
#define APADH 72
#define PPADH 72
#define OQ_B 0
#define OK_B (QROWS * APADH * 2)                 // 9216
#define OV_B (OK_B + 2 * KT * APADH * 2)         // 27648
#define OP_B (OV_B + KT * APADH * 2)             // 36864
#define OPART_B (OP_B + QROWS * PPADH * 2)       // 46080
#define ORINV_B (OPART_B + 4 * QROWS * 4)        // 47104
#define ATTN_SMEM (ORINV_B + QROWS * 4)          // 47360 (x4 = 185 KB/SM)

__global__ void __launch_bounds__(256, 4)
attn_fused(const __half* __restrict__ Q, const __half* __restrict__ Kg,
           const __half* __restrict__ Vg, float* __restrict__ attn,
           __half* __restrict__ O) {
    char* smb = smraw;
    __half* Ps = (__half*)(smb + OP_B);
    float* part = (float*)(smb + OPART_B);  // [4][64]
    float* rinv = (float*)(smb + ORINV_B);  // [64]

    int bh = blockIdx.y;
    int b = bh / HH, h = bh % HH;
    int q0 = blockIdx.x * QROWS;
    const __half* Qb = Q + (size_t)b * NQ * DD + h * HDIM;
    const __half* Kb = Kg + (size_t)b * NK * DD + h * HDIM;
    const __half* Vb = Vg + (size_t)b * NK * DD + h * HDIM;
    float* outP = attn + (size_t)bh * NQ * NK;

    int tid = threadIdx.x;
    int warp = tid >> 5, lane = tid & 31;
    int g = lane >> 2, tig = lane & 3;
    int wm = warp >> 2, wn = warp & 3;      // 2x4 (S): 32x16 warp tiles
    int wm2 = warp >> 1, wn2 = warp & 1;    // 4x2 (PV): 16x32 warp tiles

    uint32_t smB = (uint32_t)__cvta_generic_to_shared(smb);
    uint32_t qsB = smB + OQ_B;
    uint32_t ksB = smB + OK_B;
    uint32_t vsB = smB + OV_B;
    uint32_t psB = smB + OP_B;

    uint32_t qA   = qsB + ((wm * 32 + (lane & 15)) * APADH + (lane >> 4) * 8) * 2;
    uint32_t kOff = ((wn * 16 + (lane & 7)) * APADH + ((lane >> 3) & 1) * 8) * 2;
    uint32_t pA   = psB + ((wm2 * 16 + (lane & 15)) * PPADH + (lane >> 4) * 8) * 2;
    uint32_t vA   = vsB + (((lane & 7) + ((lane >> 3) & 1) * 8) * APADH) * 2;

#define KSTAGE(buf, kt)                                                          \
    do {                                                                         \
        _Pragma("unroll")                                                        \
        for (int i = 0; i < 2; i++) {                                            \
            int idx = tid + i * 256;                                             \
            int r = idx >> 3, c8 = (idx & 7) * 8;                                \
            cpa16(ksB + ((buf) * KT * APADH + r * APADH + c8) * 2,               \
                  Kb + (size_t)((kt) * KT + r) * DD + c8);                       \
        }                                                                        \
        cp_commit();                                                             \
    } while (0)

#define VSTAGE(kt)                                                               \
    do {                                                                         \
        _Pragma("unroll")                                                        \
        for (int i = 0; i < 2; i++) {                                            \
            int idx = tid + i * 256;                                             \
            int r = idx >> 3, c8 = (idx & 7) * 8;                                \
            cpa16(vsB + (r * APADH + c8) * 2,                                    \
                  Vb + (size_t)((kt) * KT + r) * DD + c8);                       \
        }                                                                        \
        cp_commit();                                                             \
    } while (0)

    // Stage Q tile (fp16, prescaled by 0.125 upstream): 64 rows x 64 cols.
#pragma unroll
    for (int i = 0; i < 2; i++) {
        int idx = tid + i * 256;
        int r = idx >> 3, c8 = (idx & 7) * 8;
        cpa16(qsB + (r * APADH + c8) * 2, Qb + (size_t)(q0 + r) * DD + c8);
    }
    cp_commit();
    cp_wait0();
    __syncthreads();

    // ---------------- Pass 1: row sums of exp(S) ----------------
    float rs[4] = {};
    KSTAGE(0, 0);
    for (int kt = 0; kt < NKT; kt++) {
        if (kt < NKT - 1) { KSTAGE((kt + 1) & 1, kt + 1); cp_wait1(); }
        else              { cp_wait0(); }
        __syncthreads();
        uint32_t kbase = ksB + (kt & 1) * KT * APADH * 2 + kOff;
        float acc[2][2][4] = {};
#pragma unroll
        for (int ks = 0; ks < 4; ks++) {
            uint32_t a[2][4], bf[2][2];
#pragma unroll
            for (int mi = 0; mi < 2; mi++)
                ldsm4(a[mi], qA + (mi * 16 * APADH + ks * 16) * 2);
#pragma unroll
            for (int ni = 0; ni < 2; ni++)
                ldsm2(bf[ni], kbase + (ni * 8 * APADH + ks * 16) * 2);
#pragma unroll
            for (int mi = 0; mi < 2; mi++)
#pragma unroll
                for (int ni = 0; ni < 2; ni++)
                    mma16(acc[mi][ni], a[mi], bf[ni]);
        }
#pragma unroll
        for (int mi = 0; mi < 2; mi++)
#pragma unroll
            for (int ni = 0; ni < 2; ni++) {
                rs[mi * 2 + 0] += __expf(acc[mi][ni][0]) + __expf(acc[mi][ni][1]);
                rs[mi * 2 + 1] += __expf(acc[mi][ni][2]) + __expf(acc[mi][ni][3]);
            }
        __syncthreads();
    }
    // Deterministic cross-warp row-sum reduction.
#pragma unroll
    for (int j = 0; j < 4; j++) {
        float v = rs[j];
        v += __shfl_xor_sync(0xffffffffu, v, 1);
        v += __shfl_xor_sync(0xffffffffu, v, 2);
        if (tig == 0)
            part[wn * QROWS + wm * 32 + (j >> 1) * 16 + g + (j & 1) * 8] = v;
    }
    __syncthreads();
    if (tid < QROWS)
        rinv[tid] = 1.0f / (part[tid] + part[QROWS + tid] +
                            part[2 * QROWS + tid] + part[3 * QROWS + tid]);
    __syncthreads();

    // ---------------- Pass 2: P out + P*V ----------------
    float acc_o[4][4] = {};
    KSTAGE(0, 0);
    for (int kt = 0; kt < NKT; kt++) {
        if (kt < NKT - 1) KSTAGE((kt + 1) & 1, kt + 1);
        VSTAGE(kt);
        if (kt < NKT - 1) cp_wait2(); else cp_wait1();   // K(kt) ready
        __syncthreads();
        uint32_t kbase = ksB + (kt & 1) * KT * APADH * 2 + kOff;
        float acc[2][2][4] = {};
#pragma unroll
        for (int ks = 0; ks < 4; ks++) {
            uint32_t a[2][4], bf[2][2];
#pragma unroll
            for (int mi = 0; mi < 2; mi++)
                ldsm4(a[mi], qA + (mi * 16 * APADH + ks * 16) * 2);
#pragma unroll
            for (int ni = 0; ni < 2; ni++)
                ldsm2(bf[ni], kbase + (ni * 8 * APADH + ks * 16) * 2);
#pragma unroll
            for (int mi = 0; mi < 2; mi++)
#pragma unroll
                for (int ni = 0; ni < 2; ni++)
                    mma16(acc[mi][ni], a[mi], bf[ni]);
        }
        // Normalize, emit P to gmem (fp32, streaming) and smem (fp16).
#pragma unroll
        for (int mi = 0; mi < 2; mi++) {
            int rl = wm * 32 + mi * 16 + g;
            float ri0 = rinv[rl], ri1 = rinv[rl + 8];
#pragma unroll
            for (int ni = 0; ni < 2; ni++) {
                int cl = wn * 16 + ni * 8 + tig * 2;
                float p0 = __expf(acc[mi][ni][0]) * ri0;
                float p1 = __expf(acc[mi][ni][1]) * ri0;
                float p2 = __expf(acc[mi][ni][2]) * ri1;
                float p3 = __expf(acc[mi][ni][3]) * ri1;
                stcs2(outP + (size_t)(q0 + rl) * NK + kt * KT + cl, p0, p1);
                stcs2(outP + (size_t)(q0 + rl + 8) * NK + kt * KT + cl, p2, p3);
                *(uint32_t*)(Ps + rl * PPADH + cl) = packh2(p0, p1);
                *(uint32_t*)(Ps + (rl + 8) * PPADH + cl) = packh2(p2, p3);
            }
        }
        if (kt < NKT - 1) cp_wait1(); else cp_wait0();   // V(kt) ready
        __syncthreads();                                 // Ps + Vs visible
        // O += P(64x64) * V(64x64): 4x2 warp grid, 16x32 tiles
#pragma unroll
        for (int ks = 0; ks < 4; ks++) {
            int k0 = ks * 16;
            uint32_t a[4], bf[4][2];
            ldsm4(a, pA + k0 * 2);
#pragma unroll
            for (int ni = 0; ni < 4; ni++) {
                int nb = wn2 * 32 + ni * 8;
                ldsm2t(bf[ni], vA + (k0 * APADH + nb) * 2);
            }
#pragma unroll
            for (int ni = 0; ni < 4; ni++)
                mma16(acc_o[ni], a, bf[ni]);
        }
        __syncthreads();
    }
#undef KSTAGE
#undef VSTAGE

    // Write O as fp16 (consumed by the fp16 out-projection GEMM).
    {
        int r = q0 + wm2 * 16 + g;
#pragma unroll
        for (int ni = 0; ni < 4; ni++) {
            int c = wn2 * 32 + ni * 8 + tig * 2;
            __half* o0 = O + ((size_t)b * NQ + r) * DD + h * HDIM + c;
            *(uint32_t*)o0 = packh2(acc_o[ni][0], acc_o[ni][1]);
            __half* o1 = O + ((size_t)b * NQ + r + 8) * DD + h * HDIM + c;
            *(uint32_t*)o1 = packh2(acc_o[ni][2], acc_o[ni][3]);
        }
    }
}

// ---------------------------------------------------------------------------
extern "C" void kernel_launch(void* const* d_in, const int* in_sizes, int n_in,
                              void* d_out, int out_size) {
    const float* q_seq   = (const float*)d_in[0];
    const float* kv_seq  = (const float*)d_in[1];
    const float* Wq      = (const float*)d_in[2];
    const float* bq      = (const float*)d_in[3];
    const float* Wk      = (const float*)d_in[4];
    const float* bk      = (const float*)d_in[5];
    const float* Wv      = (const float*)d_in[6];
    const float* bv      = (const float*)d_in[7];
    const float* Wo      = (const float*)d_in[8];
    const float* bo      = (const float*)d_in[9];
    const float* freqs_q = (const float*)d_in[10];
    const float* freqs_kv= (const float*)d_in[11];

    float* out  = (float*)d_out;
    float* attn = out + (size_t)BB * NQ * DD;

    __half *gQ, *gK, *gV, *gO, *gXq, *gXkv, *gWq, *gWk, *gWv, *gWo;
    cudaGetSymbolAddress((void**)&gQ,  g_Q);
    cudaGetSymbolAddress((void**)&gK,  g_K);
    cudaGetSymbolAddress((void**)&gV,  g_V);
    cudaGetSymbolAddress((void**)&gO,  g_O);
    cudaGetSymbolAddress((void**)&gXq, g_Xq);
    cudaGetSymbolAddress((void**)&gXkv,g_Xkv);
    cudaGetSymbolAddress((void**)&gWq, g_Wq);
    cudaGetSymbolAddress((void**)&gWk, g_Wk);
    cudaGetSymbolAddress((void**)&gWv, g_Wv);
    cudaGetSymbolAddress((void**)&gWo, g_Wo);

    static int attr_done = 0;
    if (!attr_done) {
        cudaFuncSetAttribute(gemm_bias_rope_tc,
                             cudaFuncAttributeMaxDynamicSharedMemorySize, GEMM_SMEM);
        cudaFuncSetAttribute(attn_fused,
                             cudaFuncAttributeMaxDynamicSharedMemorySize, ATTN_SMEM);
        attr_done = 1;
    }

    // Single fused pre-convert launch.
    cvt_all_kernel<<<(CVT_TOTAL + 255) / 256, 256>>>(
        (const float4*)q_seq, (const float4*)kv_seq,
        (const float4*)Wq, (const float4*)Wk, (const float4*)Wv, (const float4*)Wo,
        (uint2*)gXq, (uint2*)gXkv,
        (uint2*)gWq, (uint2*)gWk, (uint2*)gWv, (uint2*)gWo);

    dim3 gproj(DD / GBN, (BB * NQ) / GBM);   // 8 x 32 = 256 blocks, 2/SM

    gemm_bias_rope_tc<<<gproj, 256, GEMM_SMEM>>>(
        gXq, gWq, bq, gQ, BB * NQ, DD, DD, freqs_q, (float)(2 * NQ), 1.0f, 1, 1, 0.125f);
    gemm_bias_rope_tc<<<gproj, 256, GEMM_SMEM>>>(
        gXkv, gWk, bk, gK, BB * NK, DD, DD, freqs_kv, (float)(2 * NK), -1.0f, 1, 1, 1.0f);
    gemm_bias_rope_tc<<<gproj, 256, GEMM_SMEM>>>(
        gXkv, gWv, bv, gV, BB * NK, DD, DD, nullptr, 1.0f, 0.0f, 0, 1, 1.0f);

    attn_fused<<<dim3(NQ / QROWS, BB * HH), 256, ATTN_SMEM>>>(gQ, gK, gV, attn, gO);

    gemm_bias_rope_tc<<<gproj, 256, GEMM_SMEM>>>(
        gO, gWo, bo, out, BB * NQ, DD, DD, nullptr, 1.0f, 0.0f, 0, 0, 1.0f);
}